// round 6
// baseline (speedup 1.0000x reference)
#include <cuda_runtime.h>

#define N_NODES 2000
#define BATCH 512
#define N_TOTAL (BATCH * N_NODES)      // 1,024,000
#define N_EDGES (16 * N_TOTAL)         // 16,384,000
#define SLOPE 0.01f
#define SLOTS 64                       // fixed per-row capacity; max degree ~45 (Poisson 16, 1M rows)

// -------- device scratch (no allocation; BSS zero-init) --------
// Device globals are referenced ONLY from device code.
__device__ __align__(16) int   g_cursor[N_TOTAL];                 // per-row fill cursor == degree after fill
__device__ __align__(16) int   g_col[(size_t)N_TOTAL * SLOTS];    // 256 MB fixed-slot CSR
__device__ __align__(16) float g_ya[(size_t)N_TOTAL * 8];
__device__ __align__(16) float g_yb[(size_t)N_TOTAL * 8];
__device__ __align__(16) float g_z[N_TOTAL];

__device__ __forceinline__ float leaky(float v) { return v > 0.0f ? v : SLOPE * v; }

// ---------------- build: zero cursors, then slot-fill ----------------
__global__ void k_zero_cursor() {
    int t = blockIdx.x * blockDim.x + threadIdx.x;       // int4 index
    if (t < N_TOTAL / 4) reinterpret_cast<int4*>(g_cursor)[t] = make_int4(0, 0, 0, 0);
}

__global__ void k_fill(const int* __restrict__ ei) {
    unsigned e = blockIdx.x * blockDim.x + threadIdx.x;
    if (e < (unsigned)N_EDGES) {
        int src = __ldg(ei + e);
        int dst = __ldg(ei + N_EDGES + e);
        int pos = atomicAdd(&g_cursor[dst], 1);
        if (pos < SLOTS) g_col[(size_t)dst * SLOTS + pos] = src;
    }
}

// ---------------- pretransform: g_ya = x @ w0a (bias folded by linearity) ----------------
__global__ void k_pre(const float* __restrict__ x, const float* __restrict__ w0a) {
    __shared__ float sw[128];
    int t = threadIdx.x;
    if (t < 128) sw[t] = w0a[t];
    __syncthreads();
    unsigned i = blockIdx.x * blockDim.x + t;
    if (i >= (unsigned)N_TOTAL) return;
    float in[16];
    const float4* ax = reinterpret_cast<const float4*>(x + (size_t)i * 16);
#pragma unroll
    for (int q = 0; q < 4; q++) {
        float4 a = ax[q];
        in[4 * q] = a.x; in[4 * q + 1] = a.y; in[4 * q + 2] = a.z; in[4 * q + 3] = a.w;
    }
    float y[8];
#pragma unroll
    for (int j = 0; j < 8; j++) y[j] = 0.f;
#pragma unroll
    for (int k = 0; k < 16; k++) {
        float v = in[k];
#pragma unroll
        for (int j = 0; j < 8; j++) y[j] = fmaf(v, sw[k * 8 + j], y[j]);
    }
    float4* py = reinterpret_cast<float4*>(g_ya + (size_t)i * 8);
    py[0] = make_float4(y[0], y[1], y[2], y[3]);
    py[1] = make_float4(y[4], y[5], y[6], y[7]);
}

// ---------------- fused gather + MLP (+ next-layer wa) ----------------
// flip=0: read g_ya, write g_yb ; flip=1: read g_yb, write g_ya
__global__ void k_gather_mlp(int flip,
                             const float* __restrict__ ba, const float* __restrict__ wb,
                             const float* __restrict__ bb, const float* __restrict__ wan) {
    const float* yin  = flip ? g_yb : g_ya;
    float*       yout = flip ? g_ya : g_yb;

    __shared__ float swb[64], swan[64], sba[8], sbb[8];
    int t = threadIdx.x;
    if (t < 64) { swb[t] = wb[t]; swan[t] = wan[t]; }
    if (t < 8)  { sba[t] = ba[t]; sbb[t] = bb[t]; }
    __syncthreads();

    unsigned g = blockIdx.x * blockDim.x + t;   // 2 lanes per node, exact multiple
    unsigned node = g >> 1;
    unsigned half = g & 1u;

    int deg = __ldg(&g_cursor[node]);
    const int* cp = g_col + (size_t)node * SLOTS;

    // self term
    float4 acc = *reinterpret_cast<const float4*>(yin + (size_t)node * 8 + half * 4);
    int nfull = deg >> 2;
    for (int i = 0; i < nfull; i++) {
        int4 c = *reinterpret_cast<const int4*>(cp + 4 * i);
        float4 v0 = __ldg(reinterpret_cast<const float4*>(yin + (size_t)c.x * 8 + half * 4));
        float4 v1 = __ldg(reinterpret_cast<const float4*>(yin + (size_t)c.y * 8 + half * 4));
        float4 v2 = __ldg(reinterpret_cast<const float4*>(yin + (size_t)c.z * 8 + half * 4));
        float4 v3 = __ldg(reinterpret_cast<const float4*>(yin + (size_t)c.w * 8 + half * 4));
        acc.x += v0.x + v1.x + v2.x + v3.x;
        acc.y += v0.y + v1.y + v2.y + v3.y;
        acc.z += v0.z + v1.z + v2.z + v3.z;
        acc.w += v0.w + v1.w + v2.w + v3.w;
    }
    for (int r = nfull * 4; r < deg; r++) {
        int c = __ldg(cp + r);
        float4 v = __ldg(reinterpret_cast<const float4*>(yin + (size_t)c * 8 + half * 4));
        acc.x += v.x; acc.y += v.y; acc.z += v.z; acc.w += v.w;
    }

    // exchange halves with pair lane
    float o0 = __shfl_xor_sync(0xFFFFFFFFu, acc.x, 1);
    float o1 = __shfl_xor_sync(0xFFFFFFFFu, acc.y, 1);
    float o2 = __shfl_xor_sync(0xFFFFFFFFu, acc.z, 1);
    float o3 = __shfl_xor_sync(0xFFFFFFFFu, acc.w, 1);
    float in[8];
    if (half == 0) {
        in[0] = acc.x; in[1] = acc.y; in[2] = acc.z; in[3] = acc.w;
        in[4] = o0; in[5] = o1; in[6] = o2; in[7] = o3;
    } else {
        in[0] = o0; in[1] = o1; in[2] = o2; in[3] = o3;
        in[4] = acc.x; in[5] = acc.y; in[6] = acc.z; in[7] = acc.w;
    }

    float t1[8];
#pragma unroll
    for (int j = 0; j < 8; j++) t1[j] = leaky(in[j] + sba[j]);
    float t2[8];
#pragma unroll
    for (int j = 0; j < 8; j++) t2[j] = sbb[j];
#pragma unroll
    for (int k = 0; k < 8; k++) {
        float v = t1[k];
#pragma unroll
        for (int j = 0; j < 8; j++) t2[j] = fmaf(v, swb[k * 8 + j], t2[j]);
    }
#pragma unroll
    for (int j = 0; j < 8; j++) t2[j] = leaky(t2[j]);   // inter-layer act

    // next-layer pre-transform: this lane only needs its 4 output columns
    int jo = half * 4;
    float y0 = 0.f, y1 = 0.f, y2 = 0.f, y3 = 0.f;
#pragma unroll
    for (int k = 0; k < 8; k++) {
        float v = t2[k];
        y0 = fmaf(v, swan[k * 8 + jo + 0], y0);
        y1 = fmaf(v, swan[k * 8 + jo + 1], y1);
        y2 = fmaf(v, swan[k * 8 + jo + 2], y2);
        y3 = fmaf(v, swan[k * 8 + jo + 3], y3);
    }
    *reinterpret_cast<float4*>(yout + (size_t)node * 8 + half * 4) = make_float4(y0, y1, y2, y3);
}

// Last layer (reads g_yb): z = fc1( leaky( leaky(agg + b3a) @ w3b + b3b ) )
__global__ void k_gather_last(const float* __restrict__ ba, const float* __restrict__ wb,
                              const float* __restrict__ bb,
                              const float* __restrict__ fc1w, const float* __restrict__ fc1b) {
    const float* yin = g_yb;

    __shared__ float swb[64], sba[8], sbb[8], sf1[8], sf1b;
    int t = threadIdx.x;
    if (t < 64) swb[t] = wb[t];
    if (t < 8)  { sba[t] = ba[t]; sbb[t] = bb[t]; sf1[t] = fc1w[t]; }
    if (t == 0) sf1b = fc1b[0];
    __syncthreads();

    unsigned g = blockIdx.x * blockDim.x + t;
    unsigned node = g >> 1;
    unsigned half = g & 1u;

    int deg = __ldg(&g_cursor[node]);
    const int* cp = g_col + (size_t)node * SLOTS;

    float4 acc = *reinterpret_cast<const float4*>(yin + (size_t)node * 8 + half * 4);
    int nfull = deg >> 2;
    for (int i = 0; i < nfull; i++) {
        int4 c = *reinterpret_cast<const int4*>(cp + 4 * i);
        float4 v0 = __ldg(reinterpret_cast<const float4*>(yin + (size_t)c.x * 8 + half * 4));
        float4 v1 = __ldg(reinterpret_cast<const float4*>(yin + (size_t)c.y * 8 + half * 4));
        float4 v2 = __ldg(reinterpret_cast<const float4*>(yin + (size_t)c.z * 8 + half * 4));
        float4 v3 = __ldg(reinterpret_cast<const float4*>(yin + (size_t)c.w * 8 + half * 4));
        acc.x += v0.x + v1.x + v2.x + v3.x;
        acc.y += v0.y + v1.y + v2.y + v3.y;
        acc.z += v0.z + v1.z + v2.z + v3.z;
        acc.w += v0.w + v1.w + v2.w + v3.w;
    }
    for (int r = nfull * 4; r < deg; r++) {
        int c = __ldg(cp + r);
        float4 v = __ldg(reinterpret_cast<const float4*>(yin + (size_t)c * 8 + half * 4));
        acc.x += v.x; acc.y += v.y; acc.z += v.z; acc.w += v.w;
    }

    float o0 = __shfl_xor_sync(0xFFFFFFFFu, acc.x, 1);
    float o1 = __shfl_xor_sync(0xFFFFFFFFu, acc.y, 1);
    float o2 = __shfl_xor_sync(0xFFFFFFFFu, acc.z, 1);
    float o3 = __shfl_xor_sync(0xFFFFFFFFu, acc.w, 1);
    float in[8];
    if (half == 0) {
        in[0] = acc.x; in[1] = acc.y; in[2] = acc.z; in[3] = acc.w;
        in[4] = o0; in[5] = o1; in[6] = o2; in[7] = o3;
    } else {
        in[0] = o0; in[1] = o1; in[2] = o2; in[3] = o3;
        in[4] = acc.x; in[5] = acc.y; in[6] = acc.z; in[7] = acc.w;
    }

    float t1[8];
#pragma unroll
    for (int j = 0; j < 8; j++) t1[j] = leaky(in[j] + sba[j]);
    float t2[8];
#pragma unroll
    for (int j = 0; j < 8; j++) t2[j] = sbb[j];
#pragma unroll
    for (int k = 0; k < 8; k++) {
        float v = t1[k];
#pragma unroll
        for (int j = 0; j < 8; j++) t2[j] = fmaf(v, swb[k * 8 + j], t2[j]);
    }
    // no inter-layer act; readout applies leaky before fc1
    float z = sf1b;
#pragma unroll
    for (int j = 0; j < 8; j++) z = fmaf(leaky(t2[j]), sf1[j], z);
    if (half == 0) g_z[node] = z;
}

// ---------------- readout: per-graph fc2 + log_softmax ----------------
__global__ void readout_kernel(const float* __restrict__ fc2w, const float* __restrict__ fc2b,
                               float* __restrict__ out) {
    int b = blockIdx.x;
    int t = threadIdx.x;
    float s0 = 0.f, s1 = 0.f;
    const float* zb = g_z + (size_t)b * N_NODES;
    for (int n = t; n < N_NODES; n += blockDim.x) {
        float zv = leaky(zb[n]);
        float2 w = __ldg(reinterpret_cast<const float2*>(fc2w) + n);
        s0 = fmaf(zv, w.x, s0);
        s1 = fmaf(zv, w.y, s1);
    }
#pragma unroll
    for (int o = 16; o > 0; o >>= 1) {
        s0 += __shfl_down_sync(0xFFFFFFFFu, s0, o);
        s1 += __shfl_down_sync(0xFFFFFFFFu, s1, o);
    }
    __shared__ float r0[8], r1[8];
    int w = t >> 5, lane = t & 31;
    if (lane == 0) { r0[w] = s0; r1[w] = s1; }
    __syncthreads();
    if (t == 0) {
        float a0 = 0.f, a1 = 0.f;
#pragma unroll
        for (int k = 0; k < 8; k++) { a0 += r0[k]; a1 += r1[k]; }
        a0 += fc2b[0];
        a1 += fc2b[1];
        float mx = fmaxf(a0, a1);
        float lse = mx + logf(expf(a0 - mx) + expf(a1 - mx));
        out[2 * b + 0] = a0 - lse;
        out[2 * b + 1] = a1 - lse;
    }
}

extern "C" void kernel_launch(void* const* d_in, const int* in_sizes, int n_in,
                              void* d_out, int out_size) {
    const float* x  = (const float*)d_in[0];
    const int*   ei = (const int*)d_in[1];

    int base = (in_sizes[2] == 128) ? 2 : 3;   // batch_size may not be materialized

    const float* W[16];
    for (int k = 0; k < 16; k++) W[k] = (const float*)d_in[base + k];
    const float* fc1w = (const float*)d_in[base + 16];
    const float* fc1b = (const float*)d_in[base + 17];
    const float* fc2w = (const float*)d_in[base + 18];
    const float* fc2b = (const float*)d_in[base + 19];
    float* out = (float*)d_out;

    const int TB = 256;
    unsigned edgeBlocks = (N_EDGES + TB - 1) / TB;
    unsigned nodeBlocks = (N_TOTAL + TB - 1) / TB;
    unsigned pairBlocks = (N_TOTAL * 2) / TB;          // exact

    // Fixed-slot CSR build (no hist / scan / sentinel)
    k_zero_cursor<<<(N_TOTAL / 4 + TB - 1) / TB, TB>>>();
    k_fill<<<edgeBlocks, TB>>>(ei);

    // Layer pipeline (all aggregation in pre-transformed 8-wide space)
    k_pre<<<nodeBlocks, TB>>>(x, W[0]);                                   // g_ya = x @ w0a
    k_gather_mlp<<<pairBlocks, TB>>>(0, W[1], W[2], W[3], W[4]);          // L0: ya -> yb (w1a folded)
    k_gather_mlp<<<pairBlocks, TB>>>(1, W[5], W[6], W[7], W[8]);          // L1: yb -> ya
    k_gather_mlp<<<pairBlocks, TB>>>(0, W[9], W[10], W[11], W[12]);       // L2: ya -> yb
    k_gather_last<<<pairBlocks, TB>>>(W[13], W[14], W[15], fc1w, fc1b);   // L3 + fc1 -> g_z

    readout_kernel<<<BATCH, TB>>>(fc2w, fc2b, out);
}

// round 7
// speedup vs baseline: 1.2791x; 1.2791x over previous
#include <cuda_runtime.h>

#define N_NODES 2000
#define BATCH 512
#define N_TOTAL (BATCH * N_NODES)      // 1,024,000
#define N_EDGES (16 * N_TOTAL)         // 16,384,000
#define SLOPE 0.01f
#define SLOTS 64                       // max degree; Poisson(16) tail @64 over 1M nodes ~ 1e-21
#define PLANES (SLOTS / 4)             // 16 planes of int4 (4 slots each)

// -------- device scratch (no allocation; BSS zero-init) --------
// Device globals are referenced ONLY from device code.
__device__ __align__(16) int  g_cursor[N_TOTAL];                    // degree after fill
__device__ __align__(16) int4 g_colT[(size_t)PLANES * N_TOTAL];     // transposed slot planes, 256 MB (hot: low planes)
__device__ __align__(16) float g_ya[(size_t)N_TOTAL * 8];
__device__ __align__(16) float g_yb[(size_t)N_TOTAL * 8];
__device__ __align__(16) float g_z[N_TOTAL];

__device__ __forceinline__ float leaky(float v) { return v > 0.0f ? v : SLOPE * v; }

// ---------------- build: zero cursors, then transposed slot-fill ----------------
__global__ void k_zero_cursor() {
    int t = blockIdx.x * blockDim.x + threadIdx.x;       // int4 index
    if (t < N_TOTAL / 4) reinterpret_cast<int4*>(g_cursor)[t] = make_int4(0, 0, 0, 0);
}

__global__ void k_fill(const int* __restrict__ ei) {
    unsigned e = blockIdx.x * blockDim.x + threadIdx.x;
    if (e < (unsigned)N_EDGES) {
        int src = __ldg(ei + e);
        int dst = __ldg(ei + N_EDGES + e);
        int pos = atomicAdd(&g_cursor[dst], 1);
        if (pos < SLOTS) {
            // scalar element (pos&3) of int4 at plane (pos>>2), row dst
            reinterpret_cast<int*>(g_colT)[((size_t)(pos >> 2) * N_TOTAL + dst) * 4 + (pos & 3)] = src;
        }
    }
}

// ---------------- pretransform: g_ya = x @ w0a (bias folded by linearity) ----------------
__global__ void k_pre(const float* __restrict__ x, const float* __restrict__ w0a) {
    __shared__ float sw[128];
    int t = threadIdx.x;
    if (t < 128) sw[t] = w0a[t];
    __syncthreads();
    unsigned i = blockIdx.x * blockDim.x + t;
    if (i >= (unsigned)N_TOTAL) return;
    float in[16];
    const float4* ax = reinterpret_cast<const float4*>(x + (size_t)i * 16);
#pragma unroll
    for (int q = 0; q < 4; q++) {
        float4 a = ax[q];
        in[4 * q] = a.x; in[4 * q + 1] = a.y; in[4 * q + 2] = a.z; in[4 * q + 3] = a.w;
    }
    float y[8];
#pragma unroll
    for (int j = 0; j < 8; j++) y[j] = 0.f;
#pragma unroll
    for (int k = 0; k < 16; k++) {
        float v = in[k];
#pragma unroll
        for (int j = 0; j < 8; j++) y[j] = fmaf(v, sw[k * 8 + j], y[j]);
    }
    float4* py = reinterpret_cast<float4*>(g_ya + (size_t)i * 8);
    py[0] = make_float4(y[0], y[1], y[2], y[3]);
    py[1] = make_float4(y[4], y[5], y[6], y[7]);
}

// ---------------- shared gather helper (2 lanes/node, lane handles one 4-float half) ----------------
__device__ __forceinline__ float4 gather_half(const float* __restrict__ yin,
                                              unsigned node, unsigned half) {
    int deg = __ldg(&g_cursor[node]);
    if (deg > SLOTS) deg = SLOTS;

    float4 acc = *reinterpret_cast<const float4*>(yin + (size_t)node * 8 + half * 4);
    int nfull = deg >> 2;
    const int4* cpt = g_colT + node;   // stride N_TOTAL between planes
    for (int p = 0; p < nfull; p++) {
        int4 c = __ldg(cpt + (size_t)p * N_TOTAL);
        float4 v0 = __ldg(reinterpret_cast<const float4*>(yin + (size_t)c.x * 8 + half * 4));
        float4 v1 = __ldg(reinterpret_cast<const float4*>(yin + (size_t)c.y * 8 + half * 4));
        float4 v2 = __ldg(reinterpret_cast<const float4*>(yin + (size_t)c.z * 8 + half * 4));
        float4 v3 = __ldg(reinterpret_cast<const float4*>(yin + (size_t)c.w * 8 + half * 4));
        acc.x += v0.x + v1.x + v2.x + v3.x;
        acc.y += v0.y + v1.y + v2.y + v3.y;
        acc.z += v0.z + v1.z + v2.z + v3.z;
        acc.w += v0.w + v1.w + v2.w + v3.w;
    }
    int rem = deg & 3;
    if (rem) {
        int4 c = __ldg(cpt + (size_t)nfull * N_TOTAL);   // one int4; only first `rem` entries valid
        {
            float4 v = __ldg(reinterpret_cast<const float4*>(yin + (size_t)c.x * 8 + half * 4));
            acc.x += v.x; acc.y += v.y; acc.z += v.z; acc.w += v.w;
        }
        if (rem > 1) {
            float4 v = __ldg(reinterpret_cast<const float4*>(yin + (size_t)c.y * 8 + half * 4));
            acc.x += v.x; acc.y += v.y; acc.z += v.z; acc.w += v.w;
        }
        if (rem > 2) {
            float4 v = __ldg(reinterpret_cast<const float4*>(yin + (size_t)c.z * 8 + half * 4));
            acc.x += v.x; acc.y += v.y; acc.z += v.z; acc.w += v.w;
        }
    }
    return acc;
}

// ---------------- fused gather + MLP (+ next-layer wa) ----------------
// flip=0: read g_ya, write g_yb ; flip=1: read g_yb, write g_ya
__global__ void k_gather_mlp(int flip,
                             const float* __restrict__ ba, const float* __restrict__ wb,
                             const float* __restrict__ bb, const float* __restrict__ wan) {
    const float* yin  = flip ? g_yb : g_ya;
    float*       yout = flip ? g_ya : g_yb;

    __shared__ float swb[64], swan[64], sba[8], sbb[8];
    int t = threadIdx.x;
    if (t < 64) { swb[t] = wb[t]; swan[t] = wan[t]; }
    if (t < 8)  { sba[t] = ba[t]; sbb[t] = bb[t]; }
    __syncthreads();

    unsigned g = blockIdx.x * blockDim.x + t;   // 2 lanes per node, exact multiple
    unsigned node = g >> 1;
    unsigned half = g & 1u;

    float4 acc = gather_half(yin, node, half);

    // exchange halves with pair lane
    float o0 = __shfl_xor_sync(0xFFFFFFFFu, acc.x, 1);
    float o1 = __shfl_xor_sync(0xFFFFFFFFu, acc.y, 1);
    float o2 = __shfl_xor_sync(0xFFFFFFFFu, acc.z, 1);
    float o3 = __shfl_xor_sync(0xFFFFFFFFu, acc.w, 1);
    float in[8];
    if (half == 0) {
        in[0] = acc.x; in[1] = acc.y; in[2] = acc.z; in[3] = acc.w;
        in[4] = o0; in[5] = o1; in[6] = o2; in[7] = o3;
    } else {
        in[0] = o0; in[1] = o1; in[2] = o2; in[3] = o3;
        in[4] = acc.x; in[5] = acc.y; in[6] = acc.z; in[7] = acc.w;
    }

    float t1[8];
#pragma unroll
    for (int j = 0; j < 8; j++) t1[j] = leaky(in[j] + sba[j]);
    float t2[8];
#pragma unroll
    for (int j = 0; j < 8; j++) t2[j] = sbb[j];
#pragma unroll
    for (int k = 0; k < 8; k++) {
        float v = t1[k];
#pragma unroll
        for (int j = 0; j < 8; j++) t2[j] = fmaf(v, swb[k * 8 + j], t2[j]);
    }
#pragma unroll
    for (int j = 0; j < 8; j++) t2[j] = leaky(t2[j]);   // inter-layer act

    // next-layer pre-transform: this lane only needs its 4 output columns
    int jo = half * 4;
    float y0 = 0.f, y1 = 0.f, y2 = 0.f, y3 = 0.f;
#pragma unroll
    for (int k = 0; k < 8; k++) {
        float v = t2[k];
        y0 = fmaf(v, swan[k * 8 + jo + 0], y0);
        y1 = fmaf(v, swan[k * 8 + jo + 1], y1);
        y2 = fmaf(v, swan[k * 8 + jo + 2], y2);
        y3 = fmaf(v, swan[k * 8 + jo + 3], y3);
    }
    *reinterpret_cast<float4*>(yout + (size_t)node * 8 + half * 4) = make_float4(y0, y1, y2, y3);
}

// Last layer (reads g_yb): z = fc1( leaky( leaky(agg + b3a) @ w3b + b3b ) )
__global__ void k_gather_last(const float* __restrict__ ba, const float* __restrict__ wb,
                              const float* __restrict__ bb,
                              const float* __restrict__ fc1w, const float* __restrict__ fc1b) {
    const float* yin = g_yb;

    __shared__ float swb[64], sba[8], sbb[8], sf1[8], sf1b;
    int t = threadIdx.x;
    if (t < 64) swb[t] = wb[t];
    if (t < 8)  { sba[t] = ba[t]; sbb[t] = bb[t]; sf1[t] = fc1w[t]; }
    if (t == 0) sf1b = fc1b[0];
    __syncthreads();

    unsigned g = blockIdx.x * blockDim.x + t;
    unsigned node = g >> 1;
    unsigned half = g & 1u;

    float4 acc = gather_half(yin, node, half);

    float o0 = __shfl_xor_sync(0xFFFFFFFFu, acc.x, 1);
    float o1 = __shfl_xor_sync(0xFFFFFFFFu, acc.y, 1);
    float o2 = __shfl_xor_sync(0xFFFFFFFFu, acc.z, 1);
    float o3 = __shfl_xor_sync(0xFFFFFFFFu, acc.w, 1);
    float in[8];
    if (half == 0) {
        in[0] = acc.x; in[1] = acc.y; in[2] = acc.z; in[3] = acc.w;
        in[4] = o0; in[5] = o1; in[6] = o2; in[7] = o3;
    } else {
        in[0] = o0; in[1] = o1; in[2] = o2; in[3] = o3;
        in[4] = acc.x; in[5] = acc.y; in[6] = acc.z; in[7] = acc.w;
    }

    float t1[8];
#pragma unroll
    for (int j = 0; j < 8; j++) t1[j] = leaky(in[j] + sba[j]);
    float t2[8];
#pragma unroll
    for (int j = 0; j < 8; j++) t2[j] = sbb[j];
#pragma unroll
    for (int k = 0; k < 8; k++) {
        float v = t1[k];
#pragma unroll
        for (int j = 0; j < 8; j++) t2[j] = fmaf(v, swb[k * 8 + j], t2[j]);
    }
    // no inter-layer act; readout applies leaky before fc1
    float z = sf1b;
#pragma unroll
    for (int j = 0; j < 8; j++) z = fmaf(leaky(t2[j]), sf1[j], z);
    if (half == 0) g_z[node] = z;
}

// ---------------- readout: per-graph fc2 + log_softmax ----------------
__global__ void readout_kernel(const float* __restrict__ fc2w, const float* __restrict__ fc2b,
                               float* __restrict__ out) {
    int b = blockIdx.x;
    int t = threadIdx.x;
    float s0 = 0.f, s1 = 0.f;
    const float* zb = g_z + (size_t)b * N_NODES;
    for (int n = t; n < N_NODES; n += blockDim.x) {
        float zv = leaky(zb[n]);
        float2 w = __ldg(reinterpret_cast<const float2*>(fc2w) + n);
        s0 = fmaf(zv, w.x, s0);
        s1 = fmaf(zv, w.y, s1);
    }
#pragma unroll
    for (int o = 16; o > 0; o >>= 1) {
        s0 += __shfl_down_sync(0xFFFFFFFFu, s0, o);
        s1 += __shfl_down_sync(0xFFFFFFFFu, s1, o);
    }
    __shared__ float r0[8], r1[8];
    int w = t >> 5, lane = t & 31;
    if (lane == 0) { r0[w] = s0; r1[w] = s1; }
    __syncthreads();
    if (t == 0) {
        float a0 = 0.f, a1 = 0.f;
#pragma unroll
        for (int k = 0; k < 8; k++) { a0 += r0[k]; a1 += r1[k]; }
        a0 += fc2b[0];
        a1 += fc2b[1];
        float mx = fmaxf(a0, a1);
        float lse = mx + logf(expf(a0 - mx) + expf(a1 - mx));
        out[2 * b + 0] = a0 - lse;
        out[2 * b + 1] = a1 - lse;
    }
}

extern "C" void kernel_launch(void* const* d_in, const int* in_sizes, int n_in,
                              void* d_out, int out_size) {
    const float* x  = (const float*)d_in[0];
    const int*   ei = (const int*)d_in[1];

    int base = (in_sizes[2] == 128) ? 2 : 3;   // batch_size may not be materialized

    const float* W[16];
    for (int k = 0; k < 16; k++) W[k] = (const float*)d_in[base + k];
    const float* fc1w = (const float*)d_in[base + 16];
    const float* fc1b = (const float*)d_in[base + 17];
    const float* fc2w = (const float*)d_in[base + 18];
    const float* fc2b = (const float*)d_in[base + 19];
    float* out = (float*)d_out;

    const int TB = 256;
    unsigned edgeBlocks = (N_EDGES + TB - 1) / TB;
    unsigned nodeBlocks = (N_TOTAL + TB - 1) / TB;
    unsigned pairBlocks = (N_TOTAL * 2) / TB;          // exact

    // Scan-free transposed slot CSR build
    k_zero_cursor<<<(N_TOTAL / 4 + TB - 1) / TB, TB>>>();
    k_fill<<<edgeBlocks, TB>>>(ei);

    // Layer pipeline (all aggregation in pre-transformed 8-wide space)
    k_pre<<<nodeBlocks, TB>>>(x, W[0]);                                   // g_ya = x @ w0a
    k_gather_mlp<<<pairBlocks, TB>>>(0, W[1], W[2], W[3], W[4]);          // L0: ya -> yb (w1a folded)
    k_gather_mlp<<<pairBlocks, TB>>>(1, W[5], W[6], W[7], W[8]);          // L1: yb -> ya
    k_gather_mlp<<<pairBlocks, TB>>>(0, W[9], W[10], W[11], W[12]);       // L2: ya -> yb
    k_gather_last<<<pairBlocks, TB>>>(W[13], W[14], W[15], fc1w, fc1b);   // L3 + fc1 -> g_z

    readout_kernel<<<BATCH, TB>>>(fc2w, fc2b, out);
}